// round 15
// baseline (speedup 1.0000x reference)
#include <cuda_runtime.h>
#include <cuda_bf16.h>
#include <stdint.h>

// Problem constants
#define BSZ 8
#define SEQ 4096
#define HID 1024
#define NEXP 8
#define CAP 512
#define NTOK (BSZ * SEQ)           // 32768
#define NPAIR (BSZ * NEXP)         // 64
#define IDX_OFF 0
#define SCORE_OFF (NPAIR * CAP)    // 32768
#define MASK_OFF (2 * NPAIR * CAP) // 65536
#define MASK_FLOATS (NPAIR * CAP * SEQ)   // 134217728 floats = 512 MB

#define GATE_BLOCKS 1024
#define ZF_PER_BLK  32768          // floats per zero-fill block (128 KB)
#define ZF_BLOCKS_TOTAL (MASK_FLOATS / ZF_PER_BLK)   // 4096
#define ZF_BLOCKS_A 3584           // 448 MB interleaved with gate
#define ZF_BLOCKS_B 512            // 64 MB interleaved with chunk sort
#define ZF_A_FLOATS ((size_t)ZF_BLOCKS_A * ZF_PER_BLK)

#define SORT_BLOCKS 128            // 2 per pair, 2048 keys each

// Scratch (device globals; no allocation allowed)
__device__ float g_aff[NPAIR * SEQ];                  // affinity [b*8+e][s]
__device__ unsigned long long g_runs[NPAIR * 1024];   // 2 desc runs of 512 / pair

// ---------------------------------------------------------------------------
// Kernel A: gate + mask zero-fill, INTERLEAVED (groups of 9: 2 gate, 7 ZF)
// so ZF streams hide gate latency from wave 0. Gate arithmetic FROZEN
// bit-exact since R9.
// ---------------------------------------------------------------------------
__global__ __launch_bounds__(256) void gate_zf_kernel(
    const float* __restrict__ hid, const float* __restrict__ w,
    float* __restrict__ out)
{
    __shared__ float ws[NEXP * HID];
    int tid = threadIdx.x;
    int grp = blockIdx.x / 9, r = blockIdx.x % 9;

    if (r >= 2) {
        size_t zf_id = (size_t)grp * 7 + (r - 2);
        float4* dst = (float4*)(out + (size_t)MASK_OFF + zf_id * ZF_PER_BLK);
        float4 z = make_float4(0.f, 0.f, 0.f, 0.f);
#pragma unroll
        for (int q = tid; q < ZF_PER_BLK / 4; q += 256)
            dst[q] = z;
        return;
    }
    int gate_id = grp * 2 + r;   // 0..1023

    // ---- gate path (bit-exact, frozen) ----
    for (int i = tid; i < HID * NEXP; i += 256) {
        int k = i >> 3, e = i & 7;
        ws[e * HID + k] = w[i];
    }
    __syncthreads();

    int warp = tid >> 5, lane = tid & 31;
    int tok0 = (gate_id * 8 + warp) * 4;

    float acc[4][8];
#pragma unroll
    for (int t = 0; t < 4; t++)
#pragma unroll
        for (int e = 0; e < 8; e++) acc[t][e] = 0.0f;

    const float* h0 = hid + (size_t)tok0 * HID;

#pragma unroll
    for (int i = 0; i < 8; i++) {
        int kbase = i * 128 + lane * 4;
        float wreg[8][4];
#pragma unroll
        for (int e = 0; e < 8; e++)
#pragma unroll
            for (int j = 0; j < 4; j++)
                wreg[e][j] = ws[e * HID + kbase + j];
#pragma unroll
        for (int t = 0; t < 4; t++) {
            float4 h4 = *(const float4*)(h0 + (size_t)t * HID + kbase);
            float hj[4] = {h4.x, h4.y, h4.z, h4.w};
#pragma unroll
            for (int e = 0; e < 8; e++) {
#pragma unroll
                for (int j = 0; j < 4; j++)
                    acc[t][e] = __fmaf_rn(hj[j], wreg[e][j], acc[t][e]);
            }
        }
    }

#pragma unroll
    for (int off = 16; off > 0; off >>= 1) {
#pragma unroll
        for (int t = 0; t < 4; t++)
#pragma unroll
            for (int e = 0; e < 8; e++)
                acc[t][e] = __fadd_rn(acc[t][e],
                                      __shfl_xor_sync(0xFFFFFFFFu, acc[t][e], off));
    }

    if (lane < 4) {
        int tok = tok0 + lane;
        int b = tok >> 12;
        int s = tok & (SEQ - 1);

        float m = acc[lane][0];
#pragma unroll
        for (int e = 1; e < 8; e++) m = fmaxf(m, acc[lane][e]);

        float ex[8];
        float sum = 0.0f;
#pragma unroll
        for (int e = 0; e < 8; e++) {
            float d = __fsub_rn(acc[lane][e], m);
            ex[e] = expf(d);
            sum = __fadd_rn(sum, ex[e]);
        }
#pragma unroll
        for (int e = 0; e < 8; e++)
            g_aff[((size_t)(b * NEXP + e)) * SEQ + s] = __fdiv_rn(ex[e], sum);
    }
}

// ---------------------------------------------------------------------------
// Kernel B1: per half-pair (2048 keys): sort 4 chunks of 512 descending,
// then bitonic top-k merge-selection 4 -> 2 -> 1, output ONE descending run
// of 512 = exact top-512 of the 2048 (keys are distinct, comparator network
// => identical to full-sort prefix). Interleaved 1:4 with ZF blocks.
// ---------------------------------------------------------------------------
__global__ __launch_bounds__(512) void chunksort_zf_kernel(float* __restrict__ out)
{
    __shared__ unsigned long long keys[2048];
    int grp = blockIdx.x / 5, r = blockIdx.x % 5;

    if (r != 0) {
        size_t zf_id = (size_t)grp * 4 + (r - 1);       // 0..511
        float4* dst = (float4*)(out + (size_t)MASK_OFF + ZF_A_FLOATS
                                + zf_id * ZF_PER_BLK);
        float4 z = make_float4(0.f, 0.f, 0.f, 0.f);
#pragma unroll
        for (int q = threadIdx.x; q < ZF_PER_BLK / 4; q += 512)
            dst[q] = z;
        return;
    }

    int sort_id = grp;                 // 0..127
    int pair = sort_id >> 1;
    int half = sort_id & 1;
    int gbase = half * 2048;
    const float* a = g_aff + (size_t)pair * SEQ + gbase;
    int tid = threadIdx.x;

    for (int t = tid; t < 2048; t += 512) {
        unsigned int fb = __float_as_uint(a[t]);
        keys[t] = ((unsigned long long)fb << 32) | (unsigned int)(~(gbase + t));
    }
    __syncthreads();

    // Phase 1: sort each 512-chunk descending (local bitonic; 4 chunks at once)
    for (int k = 2; k <= 512; k <<= 1) {
        for (int j = k >> 1; j > 0; j >>= 1) {
#pragma unroll 2
            for (int c = tid; c < 1024; c += 512) {      // 1024 compares/stage
                int t = ((c & ~(j - 1)) << 1) | (c & (j - 1));
                int txj = t | j;
                unsigned long long x = keys[t], y = keys[txj];
                bool desc = (((t & 511) & k) == 0);      // local index dir
                if (desc ? (x < y) : (x > y)) { keys[t] = y; keys[txj] = x; }
            }
            __syncthreads();
        }
    }

    // Phase 2: merge-select (0,1)->run at 0, (2,3)->run at 1024
    {
        int m = tid >> 8, i = tid & 511;                 // 512 threads: 2... 
    }
    // 2 merges x 512 selects = 1024 ops
    for (int c = tid; c < 1024; c += 512) {
        int m = c >> 9, i = c & 511;
        int baseA = m * 1024, baseB = baseA + 512;
        unsigned long long x = keys[baseA + i], y = keys[baseB + (511 - i)];
        keys[baseA + i] = (x > y) ? x : y;               // keep max
    }
    __syncthreads();
    for (int j = 256; j > 0; j >>= 1) {                  // sort bitonic desc
        for (int c = tid; c < 512; c += 512) {
            int m = c >> 8, i = c & 255;
            int base = m * 1024;
            int t = base + (((i & ~(j - 1)) << 1) | (i & (j - 1)));
            int txj = t | j;
            unsigned long long x = keys[t], y = keys[txj];
            if (x < y) { keys[t] = y; keys[txj] = x; }
        }
        __syncthreads();
    }

    // Phase 3: merge-select (0, 1024) -> final top-512 at 0
    if (tid < 512) {
        unsigned long long x = keys[tid], y = keys[1024 + (511 - tid)];
        keys[tid] = (x > y) ? x : y;
    }
    __syncthreads();
    for (int j = 256; j > 0; j >>= 1) {
        if (tid < 256) {
            int t = ((tid & ~(j - 1)) << 1) | (tid & (j - 1));
            int txj = t | j;
            unsigned long long x = keys[t], y = keys[txj];
            if (x < y) { keys[t] = y; keys[txj] = x; }
        }
        __syncthreads();
    }

    unsigned long long* dst = g_runs + (size_t)pair * 1024 + half * 512;
    if (tid < 512) dst[tid] = keys[tid];
}

// ---------------------------------------------------------------------------
// Kernel B2: per pair, merge-select the two 512-runs -> final top-512 desc,
// then fused epilogue (indices, scores, one-hot into pre-zeroed mask).
// ---------------------------------------------------------------------------
__global__ __launch_bounds__(512) void merge_epi_kernel(float* __restrict__ out)
{
    __shared__ unsigned long long keys[1024];
    int pair = blockIdx.x;
    int tid = threadIdx.x;
    const unsigned long long* src = g_runs + (size_t)pair * 1024;

    keys[tid] = src[tid];
    keys[tid + 512] = src[tid + 512];
    __syncthreads();

    unsigned long long x = keys[tid], y = keys[512 + (511 - tid)];
    keys[tid] = (x > y) ? x : y;
    __syncthreads();
    for (int j = 256; j > 0; j >>= 1) {
        if (tid < 256) {
            int t = ((tid & ~(j - 1)) << 1) | (tid & (j - 1));
            int txj = t | j;
            unsigned long long a = keys[t], b = keys[txj];
            if (a < b) { keys[t] = b; keys[txj] = a; }
        }
        __syncthreads();
    }

    unsigned long long key = keys[tid];
    int   si = (int)(~(unsigned int)key);
    float v  = __uint_as_float((unsigned int)(key >> 32));
    int row = pair * CAP + tid;
    out[IDX_OFF + row]   = (float)si;                 // topk_indices
    out[SCORE_OFF + row] = v;                         // topk_scores
    out[MASK_OFF + (size_t)row * SEQ + si] = 1.0f;    // one-hot
}

extern "C" void kernel_launch(void* const* d_in, const int* in_sizes, int n_in,
                              void* d_out, int out_size)
{
    const float* hid = (const float*)d_in[0];   // [8, 4096, 1024] fp32
    const float* w   = (const float*)d_in[1];   // [1024, 8] fp32
    float* out = (float*)d_out;

    gate_zf_kernel<<<GATE_BLOCKS + ZF_BLOCKS_A, 256>>>(hid, w, out);      // 4608
    chunksort_zf_kernel<<<SORT_BLOCKS + ZF_BLOCKS_B, 512>>>(out);         // 640
    merge_epi_kernel<<<NPAIR, 512>>>(out);                                // 64
}